// round 6
// baseline (speedup 1.0000x reference)
#include <cuda_runtime.h>
#include <cuda_fp16.h>
#include <stdint.h>

#define MTOT  131072
#define KDIM  512
#define NQKV  1536
#define HEADS 16
#define DH    32
#define WIN   64
#define NB    2048

// ---------------- scratch (device globals; allocation-free) ----------------
__device__ __half g_xh[(size_t)MTOT * KDIM];        // x in fp16           128MB
__device__ __half g_wqkv_t[(size_t)NQKV * KDIM];    // w_qkv^T fp16        1.5MB
__device__ __half g_wproj_t[(size_t)KDIM * KDIM];   // w_proj^T fp16       0.5MB
__device__ __half g_attnout[(size_t)MTOT * KDIM];   // attention output    128MB

// ---------------- PTX helpers ----------------
__device__ __forceinline__ uint32_t smem_u32(const void* p) {
    uint32_t a;
    asm("{ .reg .u64 t; cvta.to.shared.u64 t, %1; cvt.u32.u64 %0, t; }" : "=r"(a) : "l"(p));
    return a;
}
__device__ __forceinline__ void cpasync16(uint32_t s, const void* g) {
    asm volatile("cp.async.cg.shared.global [%0], [%1], 16;\n" :: "r"(s), "l"(g));
}
__device__ __forceinline__ void ldsm_x4(uint32_t* r, const void* p) {
    uint32_t a = smem_u32(p);
    asm volatile("ldmatrix.sync.aligned.m8n8.x4.shared.b16 {%0,%1,%2,%3}, [%4];"
                 : "=r"(r[0]), "=r"(r[1]), "=r"(r[2]), "=r"(r[3]) : "r"(a));
}
__device__ __forceinline__ void ldsm_x4_t(uint32_t* r, const void* p) {
    uint32_t a = smem_u32(p);
    asm volatile("ldmatrix.sync.aligned.m8n8.x4.trans.shared.b16 {%0,%1,%2,%3}, [%4];"
                 : "=r"(r[0]), "=r"(r[1]), "=r"(r[2]), "=r"(r[3]) : "r"(a));
}
__device__ __forceinline__ void mma16816(float* c, const uint32_t* a, uint32_t b0, uint32_t b1) {
    asm volatile(
        "mma.sync.aligned.m16n8k16.row.col.f32.f16.f16.f32 "
        "{%0,%1,%2,%3},{%4,%5,%6,%7},{%8,%9},{%0,%1,%2,%3};"
        : "+f"(c[0]), "+f"(c[1]), "+f"(c[2]), "+f"(c[3])
        : "r"(a[0]), "r"(a[1]), "r"(a[2]), "r"(a[3]), "r"(b0), "r"(b1));
}
__device__ __forceinline__ uint32_t packh2(float a, float b) {
    __half2 h = __floats2half2_rn(a, b);
    return *(uint32_t*)&h;
}

// ---------------- converters ----------------
__global__ void conv_x_kernel(const float* __restrict__ x) {
    size_t i = (size_t)blockIdx.x * blockDim.x + threadIdx.x;
    float4 v = *(const float4*)(x + i * 4);
    __half2 a = __floats2half2_rn(v.x, v.y);
    __half2 b = __floats2half2_rn(v.z, v.w);
    uint2 o;
    o.x = *(uint32_t*)&a;
    o.y = *(uint32_t*)&b;
    *(uint2*)(g_xh + i * 4) = o;
}

__global__ void conv_w_kernel(const float* __restrict__ wqkv, const float* __restrict__ wproj) {
    int i = blockIdx.x * blockDim.x + threadIdx.x;
    if (i < NQKV * KDIM) {
        int n = i >> 9, k = i & 511;
        g_wqkv_t[i] = __float2half_rn(wqkv[(size_t)k * NQKV + n]);
    }
    if (i < KDIM * KDIM) {
        int n = i >> 9, k = i & 511;
        g_wproj_t[i] = __float2half_rn(wproj[(size_t)k * KDIM + n]);
    }
}

// ============================================================================
// Fused QKV-GEMM + window attention.
// One CTA: 128 x-rows (2 windows) x 1 head.
//   GEMM: C[128 x 96] = A[128 x 512] * Bt[96 x 512]^T
//   (Bt rows gathered from the q/k/v sections of w_qkv^T for this head)
//   -> q,k,v tiles to smem -> softmax(q k^T + bias) v -> g_attnout
// grid: (HEADS, MTOT/128), blockIdx.x = head (fastest -> A-panel L2 reuse)
// ============================================================================
// dynamic smem layout (halves unless noted):
//   sA   [2][128*40]      20480 B
//   sB   [2][96*40]       15360 B
//   sqkv [2 win][3][64*40] 30720 B
//   sbias[96]  (float)      384 B
//   stab [225] (float)      900 B
#define FUSED_SMEM 67872

__global__ __launch_bounds__(256) void fused_qkv_attn_kernel(
    const float* __restrict__ bias, const float* __restrict__ table) {
    extern __shared__ char smem_raw[];
    __half* sA   = (__half*)smem_raw;            // [2][128*40]
    __half* sB   = sA + 2 * 128 * 40;            // [2][96*40]
    __half* sqkv = sB + 2 * 96 * 40;             // [2][3][64*40]
    float*  sbias = (float*)(sqkv + 6 * 64 * 40);
    float*  stab  = sbias + 96;

    const int h = blockIdx.x, bm = blockIdx.y;
    const int tid = threadIdx.x, lane = tid & 31, warp = tid >> 5;
    const float qscale = 0.17677669529663687f;   // 1/sqrt(32)

    const __half* gA = g_xh + (size_t)bm * 128 * KDIM;

    if (tid < 96) sbias[tid] = bias[(tid >> 5) * 512 + h * 32 + (tid & 31)];
    if (tid < 225) stab[tid] = table[h * 225 + tid];

    // ---------------- GEMM 128x96, BK=32, double-buffered cp.async ----------------
    auto load_tile = [&](int kt, int buf) {
        #pragma unroll
        for (int c = 0; c < 4; ++c) {
            int idx = tid + c * 256;             // 0..1023, active < 896
            if (idx < 896) {
                if (idx < 512) {                 // A: 128 rows x 4 chunks
                    int row = idx >> 2, cc = idx & 3;
                    cpasync16(smem_u32(sA + buf * 128 * 40 + row * 40 + cc * 8),
                              gA + (size_t)row * KDIM + kt * 32 + cc * 8);
                } else {                         // B: 96 rows x 4 chunks
                    int j = idx - 512;
                    int row = j >> 2, cc = j & 3;
                    int sec = row >> 5, d = row & 31;
                    cpasync16(smem_u32(sB + buf * 96 * 40 + row * 40 + cc * 8),
                              g_wqkv_t + (size_t)(sec * 512 + h * 32 + d) * KDIM + kt * 32 + cc * 8);
                }
            }
        }
        asm volatile("cp.async.commit_group;\n" ::: "memory");
    };

    // warp layout: 4(m) x 2(n); warp tile 32 x 48
    const int wm = warp >> 1, wn = warp & 1;

    float acc[2][6][4];
    #pragma unroll
    for (int i = 0; i < 2; ++i)
        #pragma unroll
        for (int j = 0; j < 6; ++j)
            #pragma unroll
            for (int e = 0; e < 4; ++e) acc[i][j][e] = 0.f;

    load_tile(0, 0);
    for (int kt = 0; kt < 16; ++kt) {
        const int buf = kt & 1;
        if (kt + 1 < 16) {
            load_tile(kt + 1, buf ^ 1);
            asm volatile("cp.async.wait_group 1;\n" ::: "memory");
        } else {
            asm volatile("cp.async.wait_group 0;\n" ::: "memory");
        }
        __syncthreads();

        const __half* cA = sA + buf * 128 * 40;
        const __half* cB = sB + buf * 96 * 40;
        #pragma unroll
        for (int kk = 0; kk < 2; ++kk) {
            uint32_t af[2][4];
            #pragma unroll
            for (int mi = 0; mi < 2; ++mi) {
                int row = wm * 32 + mi * 16 + (lane & 15);
                int col = kk * 16 + ((lane >> 4) << 3);
                ldsm_x4(af[mi], &cA[row * 40 + col]);
            }
            uint32_t bf[3][4];
            #pragma unroll
            for (int nh = 0; nh < 3; ++nh) {
                int row = wn * 48 + nh * 16 + (lane & 7) + ((lane & 16) ? 8 : 0);
                int col = kk * 16 + ((lane & 8) ? 8 : 0);
                ldsm_x4(bf[nh], &cB[row * 40 + col]);
            }
            #pragma unroll
            for (int mi = 0; mi < 2; ++mi)
                #pragma unroll
                for (int ni = 0; ni < 6; ++ni)
                    mma16816(acc[mi][ni], af[mi], bf[ni >> 1][(ni & 1) * 2],
                             bf[ni >> 1][(ni & 1) * 2 + 1]);
        }
        __syncthreads();
    }

    // ---------------- epilogue: bias (+q scale) -> smem q/k/v tiles ----------------
    const int g = lane >> 2, t = lane & 3;
    #pragma unroll
    for (int mi = 0; mi < 2; ++mi) {
        #pragma unroll
        for (int ni = 0; ni < 6; ++ni) {
            int col = wn * 48 + ni * 8 + 2 * t;          // 0..95 (within one section)
            int sec = col >> 5, d = col & 31;
            float sc = (sec == 0) ? qscale : 1.0f;
            float bc0 = sbias[col], bc1 = sbias[col + 1];
            #pragma unroll
            for (int hh = 0; hh < 2; ++hh) {
                int row = wm * 32 + mi * 16 + g + hh * 8;    // 0..127
                int win = row >> 6, lr = row & 63;
                float v0 = (acc[mi][ni][hh * 2 + 0] + bc0) * sc;
                float v1 = (acc[mi][ni][hh * 2 + 1] + bc1) * sc;
                *(__half2*)(sqkv + (win * 3 + sec) * (64 * 40) + lr * 40 + d) =
                    __floats2half2_rn(v0, v1);
            }
        }
    }
    __syncthreads();

    // ---------------- attention: warps 0-3 -> window 0, warps 4-7 -> window 1 ----------------
    const int win = warp >> 2, ww = warp & 3;
    const __half* sq = sqkv + (win * 3 + 0) * (64 * 40);
    const __half* sk = sqkv + (win * 3 + 1) * (64 * 40);
    const __half* sv = sqkv + (win * 3 + 2) * (64 * 40);

    const int r0 = ww * 16;                  // this warp's 16 rows of its window
    float s[8][4];
    #pragma unroll
    for (int i = 0; i < 8; ++i)
        #pragma unroll
        for (int e = 0; e < 4; ++e) s[i][e] = 0.f;

    // S = q k^T  (q pre-scaled)
    #pragma unroll
    for (int kk = 0; kk < 2; ++kk) {
        uint32_t a[4];
        {
            int row = r0 + (lane & 15);
            int col = kk * 16 + ((lane >> 4) << 3);
            ldsm_x4(a, &sq[row * 40 + col]);
        }
        #pragma unroll
        for (int nh = 0; nh < 4; ++nh) {
            uint32_t b[4];
            int row = nh * 16 + (lane & 7) + ((lane & 16) ? 8 : 0);
            int col = kk * 16 + ((lane & 8) ? 8 : 0);
            ldsm_x4(b, &sk[row * 40 + col]);
            mma16816(s[nh * 2],     a, b[0], b[1]);
            mma16816(s[nh * 2 + 1], a, b[2], b[3]);
        }
    }

    const int i0 = r0 + g, i1 = r0 + 8 + g;
    const int ir0 = (i0 >> 3) + 7, ic0 = (i0 & 7) + 7;
    const int ir1 = (i1 >> 3) + 7, ic1 = (i1 & 7) + 7;

    float mx0 = -1e30f, mx1 = -1e30f;
    #pragma unroll
    for (int nt = 0; nt < 8; ++nt) {
        #pragma unroll
        for (int e = 0; e < 2; ++e) {
            int m = nt * 8 + 2 * t + e;
            int dr = m >> 3, dc = m & 7;
            s[nt][e]     += stab[(ir0 - dr) * 15 + (ic0 - dc)];
            s[nt][2 + e] += stab[(ir1 - dr) * 15 + (ic1 - dc)];
            mx0 = fmaxf(mx0, s[nt][e]);
            mx1 = fmaxf(mx1, s[nt][2 + e]);
        }
    }
    mx0 = fmaxf(mx0, __shfl_xor_sync(0xffffffffu, mx0, 1));
    mx0 = fmaxf(mx0, __shfl_xor_sync(0xffffffffu, mx0, 2));
    mx1 = fmaxf(mx1, __shfl_xor_sync(0xffffffffu, mx1, 1));
    mx1 = fmaxf(mx1, __shfl_xor_sync(0xffffffffu, mx1, 2));

    float sum0 = 0.f, sum1 = 0.f;
    #pragma unroll
    for (int nt = 0; nt < 8; ++nt) {
        #pragma unroll
        for (int e = 0; e < 2; ++e) {
            s[nt][e]     = __expf(s[nt][e] - mx0);     sum0 += s[nt][e];
            s[nt][2 + e] = __expf(s[nt][2 + e] - mx1); sum1 += s[nt][2 + e];
        }
    }
    sum0 += __shfl_xor_sync(0xffffffffu, sum0, 1);
    sum0 += __shfl_xor_sync(0xffffffffu, sum0, 2);
    sum1 += __shfl_xor_sync(0xffffffffu, sum1, 1);
    sum1 += __shfl_xor_sync(0xffffffffu, sum1, 2);
    const float inv0 = 1.f / sum0, inv1 = 1.f / sum1;
    #pragma unroll
    for (int nt = 0; nt < 8; ++nt) {
        s[nt][0] *= inv0; s[nt][1] *= inv0;
        s[nt][2] *= inv1; s[nt][3] *= inv1;
    }

    // O = P v   (P reused as A-fragments)
    float o[4][4];
    #pragma unroll
    for (int i = 0; i < 4; ++i)
        #pragma unroll
        for (int e = 0; e < 4; ++e) o[i][e] = 0.f;

    #pragma unroll
    for (int kk = 0; kk < 4; ++kk) {
        uint32_t pa[4];
        pa[0] = packh2(s[2 * kk][0],     s[2 * kk][1]);
        pa[1] = packh2(s[2 * kk][2],     s[2 * kk][3]);
        pa[2] = packh2(s[2 * kk + 1][0], s[2 * kk + 1][1]);
        pa[3] = packh2(s[2 * kk + 1][2], s[2 * kk + 1][3]);
        #pragma unroll
        for (int nh = 0; nh < 2; ++nh) {
            uint32_t b[4];
            int row = kk * 16 + (lane & 7) + ((lane & 8) ? 8 : 0);
            int col = nh * 16 + ((lane & 16) ? 8 : 0);
            ldsm_x4_t(b, &sv[row * 40 + col]);
            mma16816(o[nh * 2],     pa, b[0], b[1]);
            mma16816(o[nh * 2 + 1], pa, b[2], b[3]);
        }
    }

    // write O rows into g_attnout[131072, 512] at columns h*32..
    const size_t row0 = (size_t)bm * 128 + win * 64 + i0;
    const size_t row1 = (size_t)bm * 128 + win * 64 + i1;
    #pragma unroll
    for (int ni = 0; ni < 4; ++ni) {
        int col = h * 32 + ni * 8 + 2 * t;
        *(__half2*)(g_attnout + row0 * KDIM + col) = __floats2half2_rn(o[ni][0], o[ni][1]);
        *(__half2*)(g_attnout + row1 * KDIM + col) = __floats2half2_rn(o[ni][2], o[ni][3]);
    }
}

// ---------------- proj GEMM: C[128x128] = A[128x512] x Bt[128x512]^T ----------------
#define PROJ_SMEM 40960

__global__ __launch_bounds__(256) void gemm_proj_kernel(
    const float* __restrict__ bias, float* __restrict__ outf) {
    extern __shared__ char smem_raw[];
    __half* sA = (__half*)smem_raw;               // [2][128*40]
    __half* sB = sA + 2 * 128 * 40;               // [2][128*40]

    const int bn = blockIdx.x, bm = blockIdx.y;
    const int tid = threadIdx.x, lane = tid & 31, warp = tid >> 5;
    const int wm = warp >> 2, wn = warp & 3;

    const __half* gA = g_attnout + (size_t)bm * 128 * KDIM;
    const __half* gB = g_wproj_t + (size_t)bn * 128 * KDIM;

    float acc[4][4][4];
    #pragma unroll
    for (int i = 0; i < 4; ++i)
        #pragma unroll
        for (int j = 0; j < 4; ++j)
            #pragma unroll
            for (int e = 0; e < 4; ++e) acc[i][j][e] = 0.f;

    auto load_tile = [&](int kt, int buf) {
        __half* dA = sA + buf * 128 * 40;
        __half* dB = sB + buf * 128 * 40;
        #pragma unroll
        for (int c = tid; c < 512; c += 256) {
            int row = c >> 2, cc = c & 3;
            cpasync16(smem_u32(dA + row * 40 + cc * 8), gA + (size_t)row * KDIM + kt * 32 + cc * 8);
            cpasync16(smem_u32(dB + row * 40 + cc * 8), gB + (size_t)row * KDIM + kt * 32 + cc * 8);
        }
        asm volatile("cp.async.commit_group;\n" ::: "memory");
    };

    load_tile(0, 0);
    for (int kt = 0; kt < 16; ++kt) {
        const int buf = kt & 1;
        if (kt + 1 < 16) {
            load_tile(kt + 1, buf ^ 1);
            asm volatile("cp.async.wait_group 1;\n" ::: "memory");
        } else {
            asm volatile("cp.async.wait_group 0;\n" ::: "memory");
        }
        __syncthreads();

        const __half* cA = sA + buf * 128 * 40;
        const __half* cB = sB + buf * 128 * 40;
        #pragma unroll
        for (int kk = 0; kk < 2; ++kk) {
            uint32_t af[4][4];
            #pragma unroll
            for (int mi = 0; mi < 4; ++mi) {
                int row = wm * 64 + mi * 16 + (lane & 15);
                int col = kk * 16 + ((lane >> 4) << 3);
                ldsm_x4(af[mi], &cA[row * 40 + col]);
            }
            uint32_t bf[2][4];
            #pragma unroll
            for (int nh = 0; nh < 2; ++nh) {
                int row = wn * 32 + nh * 16 + (lane & 7) + ((lane & 16) ? 8 : 0);
                int col = kk * 16 + ((lane & 8) ? 8 : 0);
                ldsm_x4(bf[nh], &cB[row * 40 + col]);
            }
            #pragma unroll
            for (int mi = 0; mi < 4; ++mi)
                #pragma unroll
                for (int ni = 0; ni < 4; ++ni)
                    mma16816(acc[mi][ni], af[mi], bf[ni >> 1][(ni & 1) * 2],
                             bf[ni >> 1][(ni & 1) * 2 + 1]);
        }
        __syncthreads();
    }

    const int g = lane >> 2, t = lane & 3;
    #pragma unroll
    for (int mi = 0; mi < 4; ++mi) {
        #pragma unroll
        for (int ni = 0; ni < 4; ++ni) {
            int col = bn * 128 + wn * 32 + ni * 8 + 2 * t;
            float bc0 = bias[col], bc1 = bias[col + 1];
            #pragma unroll
            for (int hh = 0; hh < 2; ++hh) {
                int row = bm * 128 + wm * 64 + mi * 16 + g + hh * 8;
                float v0 = acc[mi][ni][hh * 2 + 0] + bc0;
                float v1 = acc[mi][ni][hh * 2 + 1] + bc1;
                *(float2*)(outf + (size_t)row * KDIM + col) = make_float2(v0, v1);
            }
        }
    }
}

// ---------------- launch ----------------
extern "C" void kernel_launch(void* const* d_in, const int* in_sizes, int n_in,
                              void* d_out, int out_size) {
    const float* x     = (const float*)d_in[0];
    const float* wqkv  = (const float*)d_in[1];
    const float* bqkv  = (const float*)d_in[2];
    const float* tab   = (const float*)d_in[3];
    const float* wproj = (const float*)d_in[4];
    const float* bproj = (const float*)d_in[5];
    float* out = (float*)d_out;

    static int attr_set = 0;
    if (!attr_set) {
        cudaFuncSetAttribute(fused_qkv_attn_kernel, cudaFuncAttributeMaxDynamicSharedMemorySize, FUSED_SMEM);
        cudaFuncSetAttribute(gemm_proj_kernel, cudaFuncAttributeMaxDynamicSharedMemorySize, PROJ_SMEM);
        attr_set = 1;
    }

    conv_x_kernel<<<65536, 256>>>(x);
    conv_w_kernel<<<3072, 256>>>(wqkv, wproj);
    fused_qkv_attn_kernel<<<dim3(HEADS, MTOT / 128), 256, FUSED_SMEM>>>(bqkv, tab);
    gemm_proj_kernel<<<dim3(KDIM / 128, MTOT / 128), 256, PROJ_SMEM>>>(bproj, out);
}